// round 8
// baseline (speedup 1.0000x reference)
#include <cuda_runtime.h>
#include <cuda_bf16.h>

#define N_NODES 100000
#define N_EDGES 1200000
#define DIM 64

// Scratch (cudaMalloc is forbidden).
__device__ float g_agg[(size_t)N_NODES * DIM];
__device__ float g_deg[N_NODES];
__device__ int   g_idx64;   // 1 if edge_index is int64, 0 if int32

// ---------------------------------------------------------------------------
// f32x2 packed helpers (sm_103a; ptxas never auto-fuses these from C++)
// ---------------------------------------------------------------------------
__device__ __forceinline__ unsigned long long ffma2(unsigned long long a,
                                                    unsigned long long b,
                                                    unsigned long long c) {
    unsigned long long d;
    asm("fma.rn.f32x2 %0, %1, %2, %3;" : "=l"(d) : "l"(a), "l"(b), "l"(c));
    return d;
}
__device__ __forceinline__ unsigned long long pack2(float lo, float hi) {
    unsigned long long r;
    asm("mov.b64 %0, {%1, %2};" : "=l"(r) : "f"(lo), "f"(hi));
    return r;
}
__device__ __forceinline__ float2 unpack2(unsigned long long a) {
    float2 r;
    asm("mov.b64 {%0, %1}, %2;" : "=f"(r.x), "=f"(r.y) : "l"(a));
    return r;
}

// ---------------------------------------------------------------------------
// Kernel 1: zero scratch + detect edge_index dtype (int64 -> odd words all 0)
// ---------------------------------------------------------------------------
__global__ void zero_kernel(const int* __restrict__ ei32) {
    if (blockIdx.x == 0 && threadIdx.x == 0) {
        int nz_odd = 0;
        for (int k = 0; k < 128; k++) nz_odd += (ei32[2 * k + 1] != 0);
        g_idx64 = (nz_odd == 0) ? 1 : 0;
    }
    const int stride = gridDim.x * blockDim.x;
    int t = blockIdx.x * blockDim.x + threadIdx.x;
    float4* agg4 = reinterpret_cast<float4*>(g_agg);
    const int total4 = N_NODES * DIM / 4;
    for (int i = t; i < total4; i += stride)
        agg4[i] = make_float4(0.f, 0.f, 0.f, 0.f);
    for (int i = t; i < N_NODES; i += stride)
        g_deg[i] = 0.f;
}

// ---------------------------------------------------------------------------
// Kernel 2: edge scatter. 16 threads/edge, vector reduction atomics.
// ---------------------------------------------------------------------------
__global__ void edge_kernel(const float* __restrict__ x,
                            const void* __restrict__ ei_raw) {
    long long t = (long long)blockIdx.x * blockDim.x + threadIdx.x;
    int e = (int)(t >> 4);
    int c = (int)(t & 15);
    if (e >= N_EDGES) return;

    long long i, j;
    if (g_idx64) {
        const long long* ei = (const long long*)ei_raw;
        i = ei[e];
        j = ei[N_EDGES + e];
    } else {
        const int* ei = (const int*)ei_raw;
        i = ei[e];
        j = ei[N_EDGES + e];
    }

    const float4* xr = reinterpret_cast<const float4*>(x + j * DIM);
    float4 v = xr[c];
    float* dst = g_agg + i * DIM + c * 4;
    asm volatile("red.global.add.v4.f32 [%0], {%1, %2, %3, %4};"
                 :: "l"(dst), "f"(v.x), "f"(v.y), "f"(v.z), "f"(v.w)
                 : "memory");
    if (c == 0) {
        atomicAdd(g_deg + i, 1.0f);
    }
}

// ---------------------------------------------------------------------------
// Kernel 3: register-blocked GEMM + ReLU + LayerNorm.
// CTA: 256 threads, 64 nodes. Thread: 8 nodes x 2 cols (c0=lane, c1=lane+32),
// k-dimension packed into f32x2 halves (summed at the end).
// TM=8 keeps regs < 85 -> spill-free at 3 CTAs/SM.
// ---------------------------------------------------------------------------
#define TM 8
#define NODES_PER_CTA 64
#define WPAD 132   // 132*4 B row stride: 16B-aligned, conflict-free LDS.128

__global__ __launch_bounds__(256, 3)
void node_kernel(const float* __restrict__ x,
                 const float* __restrict__ W,      // [64][128]
                 const float* __restrict__ bias,   // [64]
                 const float* __restrict__ gamma,  // [64]
                 const float* __restrict__ beta,   // [64]
                 float* __restrict__ out) {
    extern __shared__ float sm[];
    float* Wsh   = sm;                          // [64][WPAD]
    float* insh  = sm + 64 * WPAD;              // [64][128]
    float* shinv = insh + NODES_PER_CTA * 128;  // [64]

    const int tid  = threadIdx.x;
    const int base = blockIdx.x * NODES_PER_CTA;

    // Stage W (coalesced global read, row-padded shared write)
    for (int i = tid; i < 64 * 32; i += 256) {
        int c = i >> 5, kq = i & 31;
        *reinterpret_cast<float4*>(&Wsh[c * WPAD + kq * 4]) =
            reinterpret_cast<const float4*>(W)[i];
    }
    // Stage inverse degrees
    if (tid < NODES_PER_CTA) {
        int gn = base + tid;
        if (gn >= N_NODES) gn = N_NODES - 1;
        shinv[tid] = 1.0f / fmaxf(g_deg[gn], 1.0f);
    }
    __syncthreads();

    // Stage concat inputs: insh[n][0:64]=x[n], insh[n][64:128]=agg[n]*inv
    for (int i = tid; i < NODES_PER_CTA * 32; i += 256) {
        int n = i >> 5, kq = i & 31;
        int gn = base + n;
        if (gn >= N_NODES) gn = N_NODES - 1;   // clamp (harmless, deterministic)
        float4 v;
        if (kq < 16) {
            v = reinterpret_cast<const float4*>(x + (size_t)gn * DIM)[kq];
        } else {
            v = reinterpret_cast<const float4*>(g_agg + (size_t)gn * DIM)[kq - 16];
            float inv = shinv[n];
            v.x *= inv; v.y *= inv; v.z *= inv; v.w *= inv;
        }
        *reinterpret_cast<float4*>(&insh[n * 128 + kq * 4]) = v;
    }
    __syncthreads();

    const int tc = tid & 31;
    const int tr = tid >> 5;
    const int c0 = tc, c1 = tc + 32;

    unsigned long long acc0[TM], acc1[TM];
    {
        unsigned long long b0 = pack2(bias[c0], 0.f);
        unsigned long long b1 = pack2(bias[c1], 0.f);
        #pragma unroll
        for (int m = 0; m < TM; m++) { acc0[m] = b0; acc1[m] = b1; }
    }

    const float* w0p = Wsh + c0 * WPAD;
    const float* w1p = Wsh + c1 * WPAD;
    const float* ip  = insh + tr * TM * 128;

    #pragma unroll 4
    for (int kq = 0; kq < 32; kq++) {
        ulonglong2 wa = *reinterpret_cast<const ulonglong2*>(w0p + kq * 4);
        ulonglong2 wb = *reinterpret_cast<const ulonglong2*>(w1p + kq * 4);
        #pragma unroll
        for (int m = 0; m < TM; m++) {
            ulonglong2 iv = *reinterpret_cast<const ulonglong2*>(ip + m * 128 + kq * 4);
            acc0[m] = ffma2(iv.x, wa.x, acc0[m]);
            acc0[m] = ffma2(iv.y, wa.y, acc0[m]);
            acc1[m] = ffma2(iv.x, wb.x, acc1[m]);
            acc1[m] = ffma2(iv.y, wb.y, acc1[m]);
        }
    }

    // Epilogue: sum packed halves, ReLU, warp-wide LayerNorm (warp owns all 64
    // cols of its 8 nodes), scale/shift, store.
    float h0[TM], h1[TM], sv[TM], qv[TM];
    #pragma unroll
    for (int m = 0; m < TM; m++) {
        float2 a = unpack2(acc0[m]);
        float2 b = unpack2(acc1[m]);
        h0[m] = fmaxf(a.x + a.y, 0.f);
        h1[m] = fmaxf(b.x + b.y, 0.f);
        sv[m] = h0[m] + h1[m];
        qv[m] = h0[m] * h0[m] + h1[m] * h1[m];
    }
    #pragma unroll
    for (int off = 16; off > 0; off >>= 1) {
        #pragma unroll
        for (int m = 0; m < TM; m++) {
            sv[m] += __shfl_xor_sync(0xFFFFFFFFu, sv[m], off);
            qv[m] += __shfl_xor_sync(0xFFFFFFFFu, qv[m], off);
        }
    }
    const float ga0 = gamma[c0], ga1 = gamma[c1];
    const float be0 = beta[c0],  be1 = beta[c1];
    #pragma unroll
    for (int m = 0; m < TM; m++) {
        int gn = base + tr * TM + m;
        if (gn < N_NODES) {
            float mu   = sv[m] * (1.0f / DIM);
            float var  = qv[m] * (1.0f / DIM) - mu * mu;
            float rstd = rsqrtf(var + 1e-5f);
            out[(size_t)gn * DIM + c0] = (h0[m] - mu) * rstd * ga0 + be0;
            out[(size_t)gn * DIM + c1] = (h1[m] - mu) * rstd * ga1 + be1;
        }
    }
}

// ---------------------------------------------------------------------------
extern "C" void kernel_launch(void* const* d_in, const int* in_sizes, int n_in,
                              void* d_out, int out_size) {
    const float* x     = (const float*)d_in[0];   // [100000, 64]
    const float* W     = (const float*)d_in[1];   // [64, 128]
    const float* bias  = (const float*)d_in[2];   // [64]
    const float* gamma = (const float*)d_in[3];   // [64]
    const float* beta  = (const float*)d_in[4];   // [64]
    const void*  ei    = d_in[5];                 // [2, 1200000] int32 or int64
    float* out         = (float*)d_out;

    // 1) zero scratch + dtype detect
    zero_kernel<<<2048, 256>>>((const int*)ei);

    // 2) edge scatter: 16 threads per edge
    {
        long long threads = (long long)N_EDGES * 16;
        int blocks = (int)((threads + 255) / 256);
        edge_kernel<<<blocks, 256>>>(x, ei);
    }

    // 3) node phase: register-blocked GEMM + LN
    {
        int smem = (64 * WPAD + NODES_PER_CTA * 128 + NODES_PER_CTA) * sizeof(float);
        cudaFuncSetAttribute(node_kernel,
                             cudaFuncAttributeMaxDynamicSharedMemorySize, smem);
        int blocks = (N_NODES + NODES_PER_CTA - 1) / NODES_PER_CTA;  // 1563
        node_kernel<<<blocks, 256, smem>>>(x, W, bias, gamma, beta, out);
    }
}

// round 11
// speedup vs baseline: 1.4853x; 1.4853x over previous
#include <cuda_runtime.h>
#include <cuda_bf16.h>

#define N_NODES 100000
#define N_EDGES 1200000
#define DIM 64

// Scratch (cudaMalloc is forbidden).
__device__ float g_agg[(size_t)N_NODES * DIM];
__device__ float g_deg[N_NODES];
__device__ int   g_idx64;   // 1 if edge_index is int64, 0 if int32

// ---------------------------------------------------------------------------
// f32x2 packed helpers (sm_103; ptxas never auto-fuses these from C++)
// ---------------------------------------------------------------------------
__device__ __forceinline__ unsigned long long ffma2(unsigned long long a,
                                                    unsigned long long b,
                                                    unsigned long long c) {
    unsigned long long d;
    asm("fma.rn.f32x2 %0, %1, %2, %3;" : "=l"(d) : "l"(a), "l"(b), "l"(c));
    return d;
}
__device__ __forceinline__ unsigned long long pack2(float lo, float hi) {
    unsigned long long r;
    asm("mov.b64 %0, {%1, %2};" : "=l"(r) : "f"(lo), "f"(hi));
    return r;
}
__device__ __forceinline__ float2 unpack2(unsigned long long a) {
    float2 r;
    asm("mov.b64 {%0, %1}, %2;" : "=f"(r.x), "=f"(r.y) : "l"(a));
    return r;
}

// ---------------------------------------------------------------------------
// Kernel 1: zero scratch + detect edge_index dtype (int64 -> odd words all 0)
// ---------------------------------------------------------------------------
__global__ void zero_kernel(const int* __restrict__ ei32) {
    if (blockIdx.x == 0 && threadIdx.x == 0) {
        int nz_odd = 0;
        for (int k = 0; k < 128; k++) nz_odd += (ei32[2 * k + 1] != 0);
        g_idx64 = (nz_odd == 0) ? 1 : 0;
    }
    const int stride = gridDim.x * blockDim.x;
    int t = blockIdx.x * blockDim.x + threadIdx.x;
    float4* agg4 = reinterpret_cast<float4*>(g_agg);
    const int total4 = N_NODES * DIM / 4;
    for (int i = t; i < total4; i += stride)
        agg4[i] = make_float4(0.f, 0.f, 0.f, 0.f);
    for (int i = t; i < N_NODES; i += stride)
        g_deg[i] = 0.f;
}

// ---------------------------------------------------------------------------
// Kernel 2: edge scatter. 16 threads/edge, vector reduction atomics.
// (near its L2 floor; unchanged)
// ---------------------------------------------------------------------------
__global__ void edge_kernel(const float* __restrict__ x,
                            const void* __restrict__ ei_raw) {
    long long t = (long long)blockIdx.x * blockDim.x + threadIdx.x;
    int e = (int)(t >> 4);
    int c = (int)(t & 15);
    if (e >= N_EDGES) return;

    long long i, j;
    if (g_idx64) {
        const long long* ei = (const long long*)ei_raw;
        i = ei[e];
        j = ei[N_EDGES + e];
    } else {
        const int* ei = (const int*)ei_raw;
        i = ei[e];
        j = ei[N_EDGES + e];
    }

    const float4* xr = reinterpret_cast<const float4*>(x + j * DIM);
    float4 v = xr[c];
    float* dst = g_agg + i * DIM + c * 4;
    asm volatile("red.global.add.v4.f32 [%0], {%1, %2, %3, %4};"
                 :: "l"(dst), "f"(v.x), "f"(v.y), "f"(v.z), "f"(v.w)
                 : "memory");
    if (c == 0) {
        atomicAdd(g_deg + i, 1.0f);
    }
}

// ---------------------------------------------------------------------------
// Kernel 3: register-blocked GEMM + ReLU + LayerNorm.
// CTA: 256 threads, 128 nodes. Lane role: cg = tid&15 -> cols {cg, cg+16,
// cg+32, cg+48}; ng = (tid>>4)&1 -> node half. Warp covers 16 nodes x 64 cols.
// Each input LDS.128 feeds 8 FFMA2 (was 4) -> fma-pipe bound, not crossbar.
// ---------------------------------------------------------------------------
#define TM 8
#define NODES_PER_CTA 128
#define WPAD 132   // 528 B row stride: 16B-aligned; 16-lane weight reads = 2-way
                   // conflict on 256B payload = still the 2-wavefront minimum

__global__ __launch_bounds__(256)
void node_kernel(const float* __restrict__ x,
                 const float* __restrict__ W,      // [64][128]
                 const float* __restrict__ bias,   // [64]
                 const float* __restrict__ gamma,  // [64]
                 const float* __restrict__ beta,   // [64]
                 float* __restrict__ out) {
    extern __shared__ float sm[];
    float* Wsh   = sm;                           // [64][WPAD]
    float* insh  = sm + 64 * WPAD;               // [128][128]
    float* shinv = insh + NODES_PER_CTA * 128;   // [128]

    const int tid  = threadIdx.x;
    const int base = blockIdx.x * NODES_PER_CTA;

    // Stage W (coalesced global read, row-padded shared write)
    for (int i = tid; i < 64 * 32; i += 256) {
        int c = i >> 5, kq = i & 31;
        *reinterpret_cast<float4*>(&Wsh[c * WPAD + kq * 4]) =
            reinterpret_cast<const float4*>(W)[i];
    }
    // Stage inverse degrees
    if (tid < NODES_PER_CTA) {
        int gn = base + tid;
        if (gn >= N_NODES) gn = N_NODES - 1;
        shinv[tid] = 1.0f / fmaxf(g_deg[gn], 1.0f);
    }
    __syncthreads();

    // Stage concat inputs: insh[n][0:64]=x[n], insh[n][64:128]=agg[n]*inv
    for (int i = tid; i < NODES_PER_CTA * 32; i += 256) {
        int n = i >> 5, kq = i & 31;
        int gn = base + n;
        if (gn >= N_NODES) gn = N_NODES - 1;   // clamp (harmless, deterministic)
        float4 v;
        if (kq < 16) {
            v = reinterpret_cast<const float4*>(x + (size_t)gn * DIM)[kq];
        } else {
            v = reinterpret_cast<const float4*>(g_agg + (size_t)gn * DIM)[kq - 16];
            float inv = shinv[n];
            v.x *= inv; v.y *= inv; v.z *= inv; v.w *= inv;
        }
        *reinterpret_cast<float4*>(&insh[n * 128 + kq * 4]) = v;
    }
    __syncthreads();

    const int cg   = tid & 15;          // column group: cols cg + 16*t
    const int ng   = (tid >> 4) & 1;    // node half within warp
    const int warp = tid >> 5;
    const int nodeBase = warp * 16 + ng * TM;   // within CTA

    unsigned long long acc[4][TM];
    #pragma unroll
    for (int t = 0; t < 4; t++) {
        unsigned long long b = pack2(bias[cg + 16 * t], 0.f);
        #pragma unroll
        for (int m = 0; m < TM; m++) acc[t][m] = b;
    }

    const float* ip = insh + nodeBase * 128;
    const float* wp0 = Wsh + (cg +  0) * WPAD;
    const float* wp1 = Wsh + (cg + 16) * WPAD;
    const float* wp2 = Wsh + (cg + 32) * WPAD;
    const float* wp3 = Wsh + (cg + 48) * WPAD;

    #pragma unroll 4
    for (int kq = 0; kq < 32; kq++) {
        ulonglong2 w0 = *reinterpret_cast<const ulonglong2*>(wp0 + kq * 4);
        ulonglong2 w1 = *reinterpret_cast<const ulonglong2*>(wp1 + kq * 4);
        ulonglong2 w2 = *reinterpret_cast<const ulonglong2*>(wp2 + kq * 4);
        ulonglong2 w3 = *reinterpret_cast<const ulonglong2*>(wp3 + kq * 4);
        #pragma unroll
        for (int m = 0; m < TM; m++) {
            ulonglong2 iv = *reinterpret_cast<const ulonglong2*>(ip + m * 128 + kq * 4);
            acc[0][m] = ffma2(iv.x, w0.x, acc[0][m]);
            acc[0][m] = ffma2(iv.y, w0.y, acc[0][m]);
            acc[1][m] = ffma2(iv.x, w1.x, acc[1][m]);
            acc[1][m] = ffma2(iv.y, w1.y, acc[1][m]);
            acc[2][m] = ffma2(iv.x, w2.x, acc[2][m]);
            acc[2][m] = ffma2(iv.y, w2.y, acc[2][m]);
            acc[3][m] = ffma2(iv.x, w3.x, acc[3][m]);
            acc[3][m] = ffma2(iv.y, w3.y, acc[3][m]);
        }
    }

    // Epilogue: halves -> ReLU; LayerNorm reduced over the 16-lane col group
    // (each 16-lane group holds all 64 cols of its 8 nodes).
    float h[4][TM], sv[TM], qv[TM];
    #pragma unroll
    for (int m = 0; m < TM; m++) {
        float s = 0.f, q = 0.f;
        #pragma unroll
        for (int t = 0; t < 4; t++) {
            float2 a = unpack2(acc[t][m]);
            float v = fmaxf(a.x + a.y, 0.f);
            h[t][m] = v;
            s += v;
            q += v * v;
        }
        sv[m] = s; qv[m] = q;
    }
    #pragma unroll
    for (int off = 8; off > 0; off >>= 1) {       // xor<16: stays within group
        #pragma unroll
        for (int m = 0; m < TM; m++) {
            sv[m] += __shfl_xor_sync(0xFFFFFFFFu, sv[m], off);
            qv[m] += __shfl_xor_sync(0xFFFFFFFFu, qv[m], off);
        }
    }

    float ga[4], be[4];
    #pragma unroll
    for (int t = 0; t < 4; t++) {
        ga[t] = gamma[cg + 16 * t];
        be[t] = beta[cg + 16 * t];
    }
    #pragma unroll
    for (int m = 0; m < TM; m++) {
        int gn = base + nodeBase + m;
        if (gn < N_NODES) {
            float mu   = sv[m] * (1.0f / DIM);
            float var  = qv[m] * (1.0f / DIM) - mu * mu;
            float rstd = rsqrtf(var + 1e-5f);
            float* op = out + (size_t)gn * DIM + cg;
            #pragma unroll
            for (int t = 0; t < 4; t++)
                op[16 * t] = (h[t][m] - mu) * rstd * ga[t] + be[t];
        }
    }
}

// ---------------------------------------------------------------------------
extern "C" void kernel_launch(void* const* d_in, const int* in_sizes, int n_in,
                              void* d_out, int out_size) {
    const float* x     = (const float*)d_in[0];   // [100000, 64]
    const float* W     = (const float*)d_in[1];   // [64, 128]
    const float* bias  = (const float*)d_in[2];   // [64]
    const float* gamma = (const float*)d_in[3];   // [64]
    const float* beta  = (const float*)d_in[4];   // [64]
    const void*  ei    = d_in[5];                 // [2, 1200000] int32 or int64
    float* out         = (float*)d_out;

    // 1) zero scratch + dtype detect
    zero_kernel<<<2048, 256>>>((const int*)ei);

    // 2) edge scatter: 16 threads per edge
    {
        long long threads = (long long)N_EDGES * 16;
        int blocks = (int)((threads + 255) / 256);
        edge_kernel<<<blocks, 256>>>(x, ei);
    }

    // 3) node phase: 4-col register-blocked GEMM + LN
    {
        int smem = (64 * WPAD + NODES_PER_CTA * 128 + NODES_PER_CTA) * sizeof(float);
        cudaFuncSetAttribute(node_kernel,
                             cudaFuncAttributeMaxDynamicSharedMemorySize, smem);
        int blocks = (N_NODES + NODES_PER_CTA - 1) / NODES_PER_CTA;  // 782
        node_kernel<<<blocks, 256, smem>>>(x, W, bias, gamma, beta, out);
    }
}

// round 12
// speedup vs baseline: 1.5525x; 1.0452x over previous
#include <cuda_runtime.h>
#include <cuda_bf16.h>

#define N_NODES 100000
#define N_EDGES 1200000
#define DIM 64

// Scratch (cudaMalloc is forbidden).
__device__ float g_agg[(size_t)N_NODES * DIM];
__device__ float g_deg[N_NODES];
__device__ int   g_idx64;   // 1 if edge_index is int64, 0 if int32

// ---------------------------------------------------------------------------
// f32x2 packed helpers (sm_103; ptxas never auto-fuses these from C++)
// ---------------------------------------------------------------------------
__device__ __forceinline__ unsigned long long ffma2(unsigned long long a,
                                                    unsigned long long b,
                                                    unsigned long long c) {
    unsigned long long d;
    asm("fma.rn.f32x2 %0, %1, %2, %3;" : "=l"(d) : "l"(a), "l"(b), "l"(c));
    return d;
}
__device__ __forceinline__ float2 unpack2(unsigned long long a) {
    float2 r;
    asm("mov.b64 {%0, %1}, %2;" : "=f"(r.x), "=f"(r.y) : "l"(a));
    return r;
}

// ---------------------------------------------------------------------------
// Kernel 1: zero scratch + detect edge_index dtype (int64 -> odd words all 0)
// ---------------------------------------------------------------------------
__global__ void zero_kernel(const int* __restrict__ ei32) {
    if (blockIdx.x == 0 && threadIdx.x == 0) {
        int nz_odd = 0;
        for (int k = 0; k < 128; k++) nz_odd += (ei32[2 * k + 1] != 0);
        g_idx64 = (nz_odd == 0) ? 1 : 0;
    }
    const int stride = gridDim.x * blockDim.x;
    int t = blockIdx.x * blockDim.x + threadIdx.x;
    float4* agg4 = reinterpret_cast<float4*>(g_agg);
    const int total4 = N_NODES * DIM / 4;
    for (int i = t; i < total4; i += stride)
        agg4[i] = make_float4(0.f, 0.f, 0.f, 0.f);
    for (int i = t; i < N_NODES; i += stride)
        g_deg[i] = 0.f;
}

// ---------------------------------------------------------------------------
// Kernel 2: edge scatter. 16 threads/edge, vector reduction atomics.
// (near its L2/RED floor; unchanged)
// ---------------------------------------------------------------------------
__global__ void edge_kernel(const float* __restrict__ x,
                            const void* __restrict__ ei_raw) {
    long long t = (long long)blockIdx.x * blockDim.x + threadIdx.x;
    int e = (int)(t >> 4);
    int c = (int)(t & 15);
    if (e >= N_EDGES) return;

    long long i, j;
    if (g_idx64) {
        const long long* ei = (const long long*)ei_raw;
        i = ei[e];
        j = ei[N_EDGES + e];
    } else {
        const int* ei = (const int*)ei_raw;
        i = ei[e];
        j = ei[N_EDGES + e];
    }

    const float4* xr = reinterpret_cast<const float4*>(x + j * DIM);
    float4 v = xr[c];
    float* dst = g_agg + i * DIM + c * 4;
    asm volatile("red.global.add.v4.f32 [%0], {%1, %2, %3, %4};"
                 :: "l"(dst), "f"(v.x), "f"(v.y), "f"(v.z), "f"(v.w)
                 : "memory");
    if (c == 0) {
        atomicAdd(g_deg + i, 1.0f);
    }
}

// ---------------------------------------------------------------------------
// Kernel 3: register-blocked GEMM + ReLU + LayerNorm.
// CTA: 256 threads, 64 nodes (3 CTAs/SM -> 768 threads resident).
// Lane role: cg = tid&15 -> cols {cg, cg+16, cg+32, cg+48};
// ng = (tid>>4)&1 -> node half. Warp covers 8 nodes x 64 cols (TM=4).
// ---------------------------------------------------------------------------
#define TM 4
#define NODES_PER_CTA 64
#define WPAD 132   // 528 B row stride: 16B-aligned

__global__ __launch_bounds__(256, 3)
void node_kernel(const float* __restrict__ x,
                 const float* __restrict__ W,      // [64][128]
                 const float* __restrict__ bias,   // [64]
                 const float* __restrict__ gamma,  // [64]
                 const float* __restrict__ beta,   // [64]
                 float* __restrict__ out) {
    extern __shared__ float sm[];
    float* Wsh   = sm;                           // [64][WPAD]
    float* insh  = sm + 64 * WPAD;               // [64][128]
    float* shinv = insh + NODES_PER_CTA * 128;   // [64]

    const int tid  = threadIdx.x;
    const int base = blockIdx.x * NODES_PER_CTA;

    // Stage W (coalesced global read, row-padded shared write)
    for (int i = tid; i < 64 * 32; i += 256) {
        int c = i >> 5, kq = i & 31;
        *reinterpret_cast<float4*>(&Wsh[c * WPAD + kq * 4]) =
            reinterpret_cast<const float4*>(W)[i];
    }
    // Stage inverse degrees
    if (tid < NODES_PER_CTA) {
        int gn = base + tid;
        if (gn >= N_NODES) gn = N_NODES - 1;
        shinv[tid] = 1.0f / fmaxf(g_deg[gn], 1.0f);
    }
    __syncthreads();

    // Stage concat inputs: insh[n][0:64]=x[n], insh[n][64:128]=agg[n]*inv
    for (int i = tid; i < NODES_PER_CTA * 32; i += 256) {
        int n = i >> 5, kq = i & 31;
        int gn = base + n;
        if (gn >= N_NODES) gn = N_NODES - 1;   // clamp (harmless, deterministic)
        float4 v;
        if (kq < 16) {
            v = reinterpret_cast<const float4*>(x + (size_t)gn * DIM)[kq];
        } else {
            v = reinterpret_cast<const float4*>(g_agg + (size_t)gn * DIM)[kq - 16];
            float inv = shinv[n];
            v.x *= inv; v.y *= inv; v.z *= inv; v.w *= inv;
        }
        *reinterpret_cast<float4*>(&insh[n * 128 + kq * 4]) = v;
    }
    __syncthreads();

    const int cg   = tid & 15;          // column group: cols cg + 16*t
    const int ng   = (tid >> 4) & 1;    // node half within warp
    const int warp = tid >> 5;
    const int nodeBase = warp * 8 + ng * TM;   // within CTA

    unsigned long long acc[4][TM];
    #pragma unroll
    for (int t = 0; t < 4; t++)
        #pragma unroll
        for (int m = 0; m < TM; m++) acc[t][m] = 0ull;

    const float* ip  = insh + nodeBase * 128;
    const float* wp0 = Wsh + (cg +  0) * WPAD;
    const float* wp1 = Wsh + (cg + 16) * WPAD;
    const float* wp2 = Wsh + (cg + 32) * WPAD;
    const float* wp3 = Wsh + (cg + 48) * WPAD;

    #pragma unroll 4
    for (int kq = 0; kq < 32; kq++) {
        ulonglong2 w0 = *reinterpret_cast<const ulonglong2*>(wp0 + kq * 4);
        ulonglong2 w1 = *reinterpret_cast<const ulonglong2*>(wp1 + kq * 4);
        ulonglong2 w2 = *reinterpret_cast<const ulonglong2*>(wp2 + kq * 4);
        ulonglong2 w3 = *reinterpret_cast<const ulonglong2*>(wp3 + kq * 4);
        #pragma unroll
        for (int m = 0; m < TM; m++) {
            ulonglong2 iv = *reinterpret_cast<const ulonglong2*>(ip + m * 128 + kq * 4);
            acc[0][m] = ffma2(iv.x, w0.x, acc[0][m]);
            acc[0][m] = ffma2(iv.y, w0.y, acc[0][m]);
            acc[1][m] = ffma2(iv.x, w1.x, acc[1][m]);
            acc[1][m] = ffma2(iv.y, w1.y, acc[1][m]);
            acc[2][m] = ffma2(iv.x, w2.x, acc[2][m]);
            acc[2][m] = ffma2(iv.y, w2.y, acc[2][m]);
            acc[3][m] = ffma2(iv.x, w3.x, acc[3][m]);
            acc[3][m] = ffma2(iv.y, w3.y, acc[3][m]);
        }
    }

    // Epilogue: halves + bias -> ReLU; LayerNorm over the 16-lane col group
    // (each 16-lane group holds all 64 cols of its TM nodes).
    float bi[4];
    #pragma unroll
    for (int t = 0; t < 4; t++) bi[t] = bias[cg + 16 * t];

    float h[4][TM], sv[TM], qv[TM];
    #pragma unroll
    for (int m = 0; m < TM; m++) {
        float s = 0.f, q = 0.f;
        #pragma unroll
        for (int t = 0; t < 4; t++) {
            float2 a = unpack2(acc[t][m]);
            float v = fmaxf(a.x + a.y + bi[t], 0.f);
            h[t][m] = v;
            s += v;
            q += v * v;
        }
        sv[m] = s; qv[m] = q;
    }
    #pragma unroll
    for (int off = 8; off > 0; off >>= 1) {       // xor<16: stays within group
        #pragma unroll
        for (int m = 0; m < TM; m++) {
            sv[m] += __shfl_xor_sync(0xFFFFFFFFu, sv[m], off);
            qv[m] += __shfl_xor_sync(0xFFFFFFFFu, qv[m], off);
        }
    }

    float ga[4], be[4];
    #pragma unroll
    for (int t = 0; t < 4; t++) {
        ga[t] = gamma[cg + 16 * t];
        be[t] = beta[cg + 16 * t];
    }
    #pragma unroll
    for (int m = 0; m < TM; m++) {
        int gn = base + nodeBase + m;
        if (gn < N_NODES) {
            float mu   = sv[m] * (1.0f / DIM);
            float var  = qv[m] * (1.0f / DIM) - mu * mu;
            float rstd = rsqrtf(var + 1e-5f);
            float* op = out + (size_t)gn * DIM + cg;
            #pragma unroll
            for (int t = 0; t < 4; t++)
                op[16 * t] = (h[t][m] - mu) * rstd * ga[t] + be[t];
        }
    }
}

// ---------------------------------------------------------------------------
extern "C" void kernel_launch(void* const* d_in, const int* in_sizes, int n_in,
                              void* d_out, int out_size) {
    const float* x     = (const float*)d_in[0];   // [100000, 64]
    const float* W     = (const float*)d_in[1];   // [64, 128]
    const float* bias  = (const float*)d_in[2];   // [64]
    const float* gamma = (const float*)d_in[3];   // [64]
    const float* beta  = (const float*)d_in[4];   // [64]
    const void*  ei    = d_in[5];                 // [2, 1200000] int32 or int64
    float* out         = (float*)d_out;

    // 1) zero scratch + dtype detect
    zero_kernel<<<2048, 256>>>((const int*)ei);

    // 2) edge scatter: 16 threads per edge
    {
        long long threads = (long long)N_EDGES * 16;
        int blocks = (int)((threads + 255) / 256);
        edge_kernel<<<blocks, 256>>>(x, ei);
    }

    // 3) node phase: 4-col register-blocked GEMM + LN, 3 CTAs/SM
    {
        int smem = (64 * WPAD + NODES_PER_CTA * 128 + NODES_PER_CTA) * sizeof(float);
        cudaFuncSetAttribute(node_kernel,
                             cudaFuncAttributeMaxDynamicSharedMemorySize, smem);
        int blocks = (N_NODES + NODES_PER_CTA - 1) / NODES_PER_CTA;  // 1563
        node_kernel<<<blocks, 256, smem>>>(x, W, bias, gamma, beta, out);
    }
}